// round 2
// baseline (speedup 1.0000x reference)
#include <cuda_runtime.h>
#include <cuda_bf16.h>
#include <cstdint>

// Chamfer loss, B=8, N=M=4096, D=3, on sm_103a.
// Fully fused single kernel:
//  - grid (64, 8, 2): 1024 blocks x 64 threads; blockIdx.z selects direction.
//  - Each thread owns ONE query point; scans all 4096 targets from SMEM tiles.
//  - Targets packed pairwise for fma.rn.f32x2 (FFMA2): per 2 targets it is
//      2x LDS.128 (broadcast) + 3x FFMA2 + 2x FMNMX
//    with two independent min accumulators (no FMNMX RAW chain).
//  - Final scalar produced inside the kernel via the threadfence-reduction
//    pattern (atomicInc wraps -> counter self-resets; fixed-order float sums
//    -> deterministic).

#define B_DIM   8
#define NPTS    4096
#define TPB     64
#define TILE    2048                       // targets per smem tile
#define QBLK    (NPTS / TPB)               // 64 blocks along queries
#define GRIDN   (QBLK * B_DIM * 2)         // 1024 blocks total

__device__ float        g_partials[GRIDN];
__device__ unsigned int g_count;           // zero-initialized device global

__device__ __forceinline__ unsigned long long pack2(float lo, float hi) {
    unsigned long long r;
    asm("mov.b64 %0, {%1, %2};" : "=l"(r) : "f"(lo), "f"(hi));
    return r;
}

__global__ __launch_bounds__(TPB) void chamfer_fused_kernel(
    const float* __restrict__ in_pts,
    const float* __restrict__ tg_pts,
    float* __restrict__ out)
{
    const int dir = blockIdx.z;
    const float* __restrict__ qset = dir ? tg_pts : in_pts;
    const float* __restrict__ tset = dir ? in_pts : tg_pts;
    const int b   = blockIdx.y;
    const int tid = threadIdx.x;
    const int qi  = blockIdx.x * TPB + tid;

    // Query point: precompute -2*x packed as f32x2 (same value both halves).
    const float* qp = qset + ((size_t)b * NPTS + qi) * 3;
    const float x0 = qp[0], x1 = qp[1], x2 = qp[2];
    const unsigned long long nx0p = pack2(-2.0f * x0, -2.0f * x0);
    const unsigned long long nx1p = pack2(-2.0f * x1, -2.0f * x1);
    const unsigned long long nx2p = pack2(-2.0f * x2, -2.0f * x2);
    const float xnorm = fmaf(x0, x0, fmaf(x1, x1, x2 * x2));

    // Paired-target tile: record r (pair of targets a,b) occupies 32 bytes:
    //   s4[2r]   = (y0a, y0b, y1a, y1b)
    //   s4[2r+1] = (y2a, y2b, |ya|^2, |yb|^2)
    __shared__ float4 s_t[TILE];           // 32 KB

    float mn0 = 3.402823466e38f;
    float mn1 = 3.402823466e38f;

    #pragma unroll
    for (int tile = 0; tile < NPTS / TILE; ++tile) {
        const float2* tb2 = (const float2*)(tset + ((size_t)b * NPTS + tile * TILE) * 3);
        __syncthreads();
        // Cooperative load: thread handles target pairs (2i, 2i+1) = 3 float2s.
        for (int i = tid; i < TILE / 2; i += TPB) {
            float2 e0 = tb2[3 * i + 0];    // (a0, a1)
            float2 e1 = tb2[3 * i + 1];    // (a2, b0)
            float2 e2 = tb2[3 * i + 2];    // (b1, b2)
            float na = fmaf(e0.x, e0.x, fmaf(e0.y, e0.y, e1.x * e1.x));
            float nb = fmaf(e1.y, e1.y, fmaf(e2.x, e2.x, e2.y * e2.y));
            s_t[2 * i]     = make_float4(e0.x, e1.y, e0.y, e2.x);  // y0a,y0b,y1a,y1b
            s_t[2 * i + 1] = make_float4(e1.x, e2.y, na,   nb);    // y2a,y2b,na,nb
        }
        __syncthreads();

        const ulonglong2* sp = (const ulonglong2*)s_t;
        #pragma unroll 8
        for (int r = 0; r < TILE / 2; ++r) {
            ulonglong2 p = sp[2 * r];        // .x=y0pair .y=y1pair  (LDS.128 bcast)
            ulonglong2 q = sp[2 * r + 1];    // .x=y2pair .y=normpair
            unsigned long long d;
            asm("fma.rn.f32x2 %0, %1, %2, %3;" : "=l"(d) : "l"(nx2p), "l"(q.x), "l"(q.y));
            asm("fma.rn.f32x2 %0, %1, %2, %3;" : "=l"(d) : "l"(nx1p), "l"(p.y), "l"(d));
            asm("fma.rn.f32x2 %0, %1, %2, %3;" : "=l"(d) : "l"(nx0p), "l"(p.x), "l"(d));
            float dlo, dhi;
            asm("mov.b64 {%0, %1}, %2;" : "=f"(dlo), "=f"(dhi) : "l"(d));
            mn0 = fminf(mn0, dlo);
            mn1 = fminf(mn1, dhi);
        }
    }

    // sqdist = max(min + |x|^2, 0), weighted by 1/(B*N) for the mean.
    float sq = fmaxf(fminf(mn0, mn1) + xnorm, 0.0f) * (1.0f / (float)(B_DIM * NPTS));

    // Deterministic block reduction (64 threads).
    __shared__ float red[TPB];
    red[tid] = sq;
    __syncthreads();
    #pragma unroll
    for (int s = TPB / 2; s > 0; s >>= 1) {
        if (tid < s) red[tid] += red[tid + s];
        __syncthreads();
    }

    // Last-block-done global reduction (threadfence reduction pattern).
    __shared__ int s_isLast;
    const int bid = (blockIdx.z * B_DIM + blockIdx.y) * QBLK + blockIdx.x;
    if (tid == 0) {
        g_partials[bid] = red[0];
        __threadfence();
        unsigned int old = atomicInc(&g_count, GRIDN - 1);  // wraps to 0 -> self-reset
        s_isLast = (old == GRIDN - 1);
    }
    __syncthreads();

    if (s_isLast) {
        // Fixed-order sum: thread t accumulates p[t], p[t+64], ... -> deterministic.
        const volatile float* vp = g_partials;
        float acc = 0.0f;
        #pragma unroll
        for (int i = 0; i < GRIDN / TPB; ++i)
            acc += vp[i * TPB + tid];
        red[tid] = acc;
        __syncthreads();
        #pragma unroll
        for (int s = TPB / 2; s > 0; s >>= 1) {
            if (tid < s) red[tid] += red[tid + s];
            __syncthreads();
        }
        if (tid == 0) out[0] = red[0];
    }
}

extern "C" void kernel_launch(void* const* d_in, const int* in_sizes, int n_in,
                              void* d_out, int out_size)
{
    const float* in_pts = (const float*)d_in[0];   // [8, 4096, 3]
    const float* tg_pts = (const float*)d_in[1];   // [8, 4096, 3]
    float* out = (float*)d_out;

    dim3 grid(QBLK, B_DIM, 2);
    chamfer_fused_kernel<<<grid, TPB>>>(in_pts, tg_pts, out);
}

// round 5
// speedup vs baseline: 1.3855x; 1.3855x over previous
#include <cuda_runtime.h>
#include <cuda_bf16.h>
#include <cstdint>

// Chamfer loss, B=8, N=M=4096, D=3, sm_103a.
// Register-blocked: each thread owns Q=4 query points (packed -2x coeffs in
// f32x2 registers); targets stream through SMEM as paired records so one
// 2-target fetch (2x LDS.128 broadcast) is reused across 4 queries:
//   per 8 pairs: 2 LDS.128 + 12 FFMA2 + 8 FMNMX  -> fma-pipe bound.
// Grid (16, 8, 2) = 256 blocks x 64 threads; fused deterministic reduction.

#define B_DIM   8
#define NPTS    4096
#define TPB     64
#define QPT     4                           // queries per thread
#define TILE    2048                        // targets per smem tile
#define QBLK    (NPTS / (TPB * QPT))        // 16 blocks along queries
#define GRIDN   (QBLK * B_DIM * 2)          // 256

__device__ float        g_partials[GRIDN];
__device__ unsigned int g_count;            // zero-init device global

__device__ __forceinline__ unsigned long long pack2(float v) {
    unsigned long long r;
    asm("mov.b64 %0, {%1, %2};" : "=l"(r) : "f"(v), "f"(v));
    return r;
}

__global__ __launch_bounds__(TPB) void chamfer_fused_kernel(
    const float* __restrict__ in_pts,
    const float* __restrict__ tg_pts,
    float* __restrict__ out)
{
    const int dir = blockIdx.z;
    const float* __restrict__ qset = dir ? tg_pts : in_pts;
    const float* __restrict__ tset = dir ? in_pts : tg_pts;
    const int b   = blockIdx.y;
    const int tid = threadIdx.x;
    const int qbase = blockIdx.x * (TPB * QPT);   // this block's 256 queries

    // Load Q=4 queries (stride-64 within the block chunk for coalescing).
    unsigned long long nx0p[QPT], nx1p[QPT], nx2p[QPT];
    float xnorm[QPT];
    #pragma unroll
    for (int qy = 0; qy < QPT; ++qy) {
        const int qi = qbase + qy * TPB + tid;
        const float* qp = qset + ((size_t)b * NPTS + qi) * 3;
        float x0 = qp[0], x1 = qp[1], x2 = qp[2];
        nx0p[qy] = pack2(-2.0f * x0);
        nx1p[qy] = pack2(-2.0f * x1);
        nx2p[qy] = pack2(-2.0f * x2);
        xnorm[qy] = fmaf(x0, x0, fmaf(x1, x1, x2 * x2));
    }

    // Paired-target records, 32 B each:
    //   s4[2r]   = (y0a, y0b, y1a, y1b)
    //   s4[2r+1] = (y2a, y2b, |ya|^2, |yb|^2)
    __shared__ float4 s_t[TILE];            // 32 KB

    float mn0[QPT], mn1[QPT];
    #pragma unroll
    for (int qy = 0; qy < QPT; ++qy) { mn0[qy] = 3.402823466e38f; mn1[qy] = 3.402823466e38f; }

    #pragma unroll
    for (int tile = 0; tile < NPTS / TILE; ++tile) {
        const float2* tb2 = (const float2*)(tset + ((size_t)b * NPTS + tile * TILE) * 3);
        __syncthreads();
        for (int i = tid; i < TILE / 2; i += TPB) {
            float2 e0 = tb2[3 * i + 0];     // (a0, a1)
            float2 e1 = tb2[3 * i + 1];     // (a2, b0)
            float2 e2 = tb2[3 * i + 2];     // (b1, b2)
            float na = fmaf(e0.x, e0.x, fmaf(e0.y, e0.y, e1.x * e1.x));
            float nb = fmaf(e1.y, e1.y, fmaf(e2.x, e2.x, e2.y * e2.y));
            s_t[2 * i]     = make_float4(e0.x, e1.y, e0.y, e2.x);
            s_t[2 * i + 1] = make_float4(e1.x, e2.y, na,   nb);
        }
        __syncthreads();

        const ulonglong2* sp = (const ulonglong2*)s_t;
        #pragma unroll 4
        for (int r = 0; r < TILE / 2; ++r) {
            const ulonglong2 p = sp[2 * r];      // y0-pair, y1-pair
            const ulonglong2 q = sp[2 * r + 1];  // y2-pair, norm-pair
            #pragma unroll
            for (int qy = 0; qy < QPT; ++qy) {
                unsigned long long d;
                asm("fma.rn.f32x2 %0, %1, %2, %3;" : "=l"(d) : "l"(nx2p[qy]), "l"(q.x), "l"(q.y));
                asm("fma.rn.f32x2 %0, %1, %2, %3;" : "=l"(d) : "l"(nx1p[qy]), "l"(p.y), "l"(d));
                asm("fma.rn.f32x2 %0, %1, %2, %3;" : "=l"(d) : "l"(nx0p[qy]), "l"(p.x), "l"(d));
                float dlo, dhi;
                asm("mov.b64 {%0, %1}, %2;" : "=f"(dlo), "=f"(dhi) : "l"(d));
                mn0[qy] = fminf(mn0[qy], dlo);
                mn1[qy] = fminf(mn1[qy], dhi);
            }
        }
    }

    // Per-thread contribution: sum over its 4 queries of clamped sqdist / (B*N).
    float sq = 0.0f;
    #pragma unroll
    for (int qy = 0; qy < QPT; ++qy)
        sq += fmaxf(fminf(mn0[qy], mn1[qy]) + xnorm[qy], 0.0f);
    sq *= (1.0f / (float)(B_DIM * NPTS));

    // Deterministic block reduction (64 threads).
    __shared__ float red[TPB];
    red[tid] = sq;
    __syncthreads();
    #pragma unroll
    for (int s = TPB / 2; s > 0; s >>= 1) {
        if (tid < s) red[tid] += red[tid + s];
        __syncthreads();
    }

    // Last-block-done global reduction.
    __shared__ int s_isLast;
    const int bid = (blockIdx.z * B_DIM + blockIdx.y) * QBLK + blockIdx.x;
    if (tid == 0) {
        g_partials[bid] = red[0];
        __threadfence();
        unsigned int old = atomicInc(&g_count, GRIDN - 1);  // wraps -> self-reset
        s_isLast = (old == GRIDN - 1);
    }
    __syncthreads();

    if (s_isLast) {
        const volatile float* vp = g_partials;
        float acc = 0.0f;
        #pragma unroll
        for (int i = 0; i < GRIDN / TPB; ++i)
            acc += vp[i * TPB + tid];
        red[tid] = acc;
        __syncthreads();
        #pragma unroll
        for (int s = TPB / 2; s > 0; s >>= 1) {
            if (tid < s) red[tid] += red[tid + s];
            __syncthreads();
        }
        if (tid == 0) out[0] = red[0];
    }
}

extern "C" void kernel_launch(void* const* d_in, const int* in_sizes, int n_in,
                              void* d_out, int out_size)
{
    const float* in_pts = (const float*)d_in[0];   // [8, 4096, 3]
    const float* tg_pts = (const float*)d_in[1];   // [8, 4096, 3]
    float* out = (float*)d_out;

    dim3 grid(QBLK, B_DIM, 2);
    chamfer_fused_kernel<<<grid, TPB>>>(in_pts, tg_pts, out);
}

// round 6
// speedup vs baseline: 1.6113x; 1.1629x over previous
#include <cuda_runtime.h>
#include <cuda_bf16.h>
#include <cstdint>

// Chamfer loss, B=8, N=M=4096, D=3, sm_103a.
// Register-blocked + target-sliced:
//  - 256 blocks (16 qchunks x 8 batch x 2 dir) x 256 threads (8 warps).
//  - Block = 4 groups of 64 threads. All groups own the SAME 256 queries
//    (QPT=4 per thread, packed -2x coeffs as f32x2); group g scans the g-th
//    quarter of the target records in the SMEM tile. Per record (2 targets
//    x 4 queries = 8 pairs): 2x LDS.128 (broadcast) + 12x FFMA2 + 8x FMNMX.
//  - Per-query mins merged across groups via SMEM; fused deterministic
//    block + grid reduction (threadfence + wrapping atomicInc).

#define B_DIM   8
#define NPTS    4096
#define TPB     256
#define GSZ     64                          // threads per group
#define NGRP    (TPB / GSZ)                 // 4 target-slice groups
#define QPT     4                           // queries per thread
#define QPB     (GSZ * QPT)                 // 256 queries per block
#define TILE    2048                        // targets per smem tile
#define RECS    (TILE / 2)                  // paired records per tile (1024)
#define RPG     (RECS / NGRP)               // records per group per tile (256)
#define QBLK    (NPTS / QPB)                // 16
#define GRIDN   (QBLK * B_DIM * 2)          // 256

__device__ float        g_partials[GRIDN];
__device__ unsigned int g_count;            // zero-init device global

__device__ __forceinline__ unsigned long long pack2(float v) {
    unsigned long long r;
    asm("mov.b64 %0, {%1, %2};" : "=l"(r) : "f"(v), "f"(v));
    return r;
}

__global__ __launch_bounds__(TPB) void chamfer_fused_kernel(
    const float* __restrict__ in_pts,
    const float* __restrict__ tg_pts,
    float* __restrict__ out)
{
    const int dir = blockIdx.z;
    const float* __restrict__ qset = dir ? tg_pts : in_pts;
    const float* __restrict__ tset = dir ? in_pts : tg_pts;
    const int b   = blockIdx.y;
    const int tid = threadIdx.x;
    const int g   = tid >> 6;               // group 0..3 (target slice)
    const int lid = tid & 63;               // lane-in-group 0..63
    const int qbase = blockIdx.x * QPB;

    // Every group loads the same 4 queries per lid (redundant across groups).
    unsigned long long nx0p[QPT], nx1p[QPT], nx2p[QPT];
    float xnorm[QPT];
    #pragma unroll
    for (int qy = 0; qy < QPT; ++qy) {
        const int qi = qbase + qy * GSZ + lid;
        const float* qp = qset + ((size_t)b * NPTS + qi) * 3;
        float x0 = qp[0], x1 = qp[1], x2 = qp[2];
        nx0p[qy] = pack2(-2.0f * x0);
        nx1p[qy] = pack2(-2.0f * x1);
        nx2p[qy] = pack2(-2.0f * x2);
        xnorm[qy] = fmaf(x0, x0, fmaf(x1, x1, x2 * x2));
    }

    // Paired-target records, 32 B each:
    //   s4[2r]   = (y0a, y0b, y1a, y1b)
    //   s4[2r+1] = (y2a, y2b, |ya|^2, |yb|^2)
    __shared__ float4 s_t[TILE];            // 32 KB (reused for min-merge)

    float mn0[QPT], mn1[QPT];
    #pragma unroll
    for (int qy = 0; qy < QPT; ++qy) { mn0[qy] = 3.402823466e38f; mn1[qy] = 3.402823466e38f; }

    #pragma unroll
    for (int tile = 0; tile < NPTS / TILE; ++tile) {
        const float2* tb2 = (const float2*)(tset + ((size_t)b * NPTS + tile * TILE) * 3);
        __syncthreads();
        for (int i = tid; i < RECS; i += TPB) {
            float2 e0 = tb2[3 * i + 0];     // (a0, a1)
            float2 e1 = tb2[3 * i + 1];     // (a2, b0)
            float2 e2 = tb2[3 * i + 2];     // (b1, b2)
            float na = fmaf(e0.x, e0.x, fmaf(e0.y, e0.y, e1.x * e1.x));
            float nb = fmaf(e1.y, e1.y, fmaf(e2.x, e2.x, e2.y * e2.y));
            s_t[2 * i]     = make_float4(e0.x, e1.y, e0.y, e2.x);
            s_t[2 * i + 1] = make_float4(e1.x, e2.y, na,   nb);
        }
        __syncthreads();

        // Group g scans records [g*RPG, (g+1)*RPG) of this tile.
        const ulonglong2* sp = (const ulonglong2*)s_t + (size_t)(2 * g * RPG);
        #pragma unroll 8
        for (int r = 0; r < RPG; ++r) {
            const ulonglong2 p = sp[2 * r];      // y0-pair, y1-pair
            const ulonglong2 q = sp[2 * r + 1];  // y2-pair, norm-pair
            #pragma unroll
            for (int qy = 0; qy < QPT; ++qy) {
                unsigned long long d;
                asm("fma.rn.f32x2 %0, %1, %2, %3;" : "=l"(d) : "l"(nx2p[qy]), "l"(q.x), "l"(q.y));
                asm("fma.rn.f32x2 %0, %1, %2, %3;" : "=l"(d) : "l"(nx1p[qy]), "l"(p.y), "l"(d));
                asm("fma.rn.f32x2 %0, %1, %2, %3;" : "=l"(d) : "l"(nx0p[qy]), "l"(p.x), "l"(d));
                float dlo, dhi;
                asm("mov.b64 {%0, %1}, %2;" : "=f"(dlo), "=f"(dhi) : "l"(d));
                mn0[qy] = fminf(mn0[qy], dlo);
                mn1[qy] = fminf(mn1[qy], dhi);
            }
        }
    }

    // ---- Merge per-query mins across the 4 groups (reuse s_t smem). ----
    __syncthreads();                         // all tile reads done
    float* s_mn  = (float*)s_t;              // [NGRP][QPB] = 1024 floats
    float* s_red = (float*)s_t + NGRP * QPB; // [TPB] reduction scratch
    #pragma unroll
    for (int qy = 0; qy < QPT; ++qy)
        s_mn[g * QPB + qy * GSZ + lid] = fminf(mn0[qy], mn1[qy]);
    __syncthreads();

    // Thread tid finalizes query index q = tid (qy = g for this thread, so
    // its own xnorm[g] is the right one; select without dynamic indexing).
    float myxn = (g == 0) ? xnorm[0] : (g == 1) ? xnorm[1] : (g == 2) ? xnorm[2] : xnorm[3];
    float mnf = s_mn[tid];
    #pragma unroll
    for (int gg = 1; gg < NGRP; ++gg)
        mnf = fminf(mnf, s_mn[gg * QPB + tid]);
    float sq = fmaxf(mnf + myxn, 0.0f) * (1.0f / (float)(B_DIM * NPTS));

    // Deterministic block reduction (256 threads).
    __syncthreads();                         // s_mn reads done before s_red writes
    s_red[tid] = sq;
    __syncthreads();
    #pragma unroll
    for (int s = TPB / 2; s > 0; s >>= 1) {
        if (tid < s) s_red[tid] += s_red[tid + s];
        __syncthreads();
    }

    // Last-block-done global reduction.
    __shared__ int s_isLast;
    const int bid = (blockIdx.z * B_DIM + blockIdx.y) * QBLK + blockIdx.x;
    if (tid == 0) {
        g_partials[bid] = s_red[0];
        __threadfence();
        unsigned int old = atomicInc(&g_count, GRIDN - 1);  // wraps -> self-reset
        s_isLast = (old == GRIDN - 1);
    }
    __syncthreads();

    if (s_isLast) {
        const volatile float* vp = g_partials;
        s_red[tid] = vp[tid];                // GRIDN == TPB == 256
        __syncthreads();
        #pragma unroll
        for (int s = TPB / 2; s > 0; s >>= 1) {
            if (tid < s) s_red[tid] += s_red[tid + s];
            __syncthreads();
        }
        if (tid == 0) out[0] = s_red[0];
    }
}

extern "C" void kernel_launch(void* const* d_in, const int* in_sizes, int n_in,
                              void* d_out, int out_size)
{
    const float* in_pts = (const float*)d_in[0];   // [8, 4096, 3]
    const float* tg_pts = (const float*)d_in[1];   // [8, 4096, 3]
    float* out = (float*)d_out;

    dim3 grid(QBLK, B_DIM, 2);
    chamfer_fused_kernel<<<grid, TPB>>>(in_pts, tg_pts, out);
}

// round 7
// speedup vs baseline: 1.8539x; 1.1506x over previous
#include <cuda_runtime.h>
#include <cuda_bf16.h>
#include <cstdint>

// Chamfer loss, B=8, N=M=4096, D=3, sm_103a.
// Round 7: target-split grid for occupancy.
//  - Grid (16, 8, 2*4) = 1024 blocks x 256 threads. z = dir*TSPLIT + ts:
//    block scans target slice [ts*1024, ts*1024+1024) for query chunk
//    blockIdx.x (256 queries) of batch blockIdx.y, direction dir.
//  - Block = 4 groups of 64 threads; all groups own the same 256 queries
//    (QPT=4/thread, -2x packed f32x2); group g scans a quarter of the
//    512 paired records. Per record (8 pairs): 2 LDS.128 + 12 FFMA2 + 8 FMNMX.
//  - In-block group merge via SMEM, then cross-block (TSPLIT) merge via
//    global slots + per-group wrapping atomicInc (deterministic fixed-order
//    min), then fused global sum via a second wrapping counter.

#define B_DIM   8
#define NPTS    4096
#define TPB     256
#define GSZ     64
#define NGRP    (TPB / GSZ)                 // 4
#define QPT     4
#define QPB     (GSZ * QPT)                 // 256 queries per block
#define TSPLIT  4
#define TILE    (NPTS / TSPLIT)             // 1024 targets per block
#define RECS    (TILE / 2)                  // 512 records
#define RPG     (RECS / NGRP)               // 128 records per group
#define QBLK    (NPTS / QPB)                // 16
#define NGROUPS (QBLK * B_DIM * 2)          // 256 merge groups
#define GRIDZ   (2 * TSPLIT)

__device__ float        g_min[NGROUPS * TSPLIT * QPB];  // raw per-slice mins
__device__ float        g_partials[NGROUPS];
__device__ unsigned int g_cnt1[NGROUPS];    // per-group arrival counters
__device__ unsigned int g_cnt2;             // global arrival counter

__device__ __forceinline__ unsigned long long pack2(float v) {
    unsigned long long r;
    asm("mov.b64 %0, {%1, %2};" : "=l"(r) : "f"(v), "f"(v));
    return r;
}

__global__ __launch_bounds__(TPB) void chamfer_fused_kernel(
    const float* __restrict__ in_pts,
    const float* __restrict__ tg_pts,
    float* __restrict__ out)
{
    const int dir = blockIdx.z / TSPLIT;
    const int ts  = blockIdx.z % TSPLIT;
    const float* __restrict__ qset = dir ? tg_pts : in_pts;
    const float* __restrict__ tset = dir ? in_pts : tg_pts;
    const int b   = blockIdx.y;
    const int tid = threadIdx.x;
    const int g   = tid >> 6;
    const int lid = tid & 63;
    const int qbase = blockIdx.x * QPB;

    // Load the 4 queries this thread scans (raw min only; xnorm added later).
    unsigned long long nx0p[QPT], nx1p[QPT], nx2p[QPT];
    #pragma unroll
    for (int qy = 0; qy < QPT; ++qy) {
        const int qi = qbase + qy * GSZ + lid;
        const float* qp = qset + ((size_t)b * NPTS + qi) * 3;
        nx0p[qy] = pack2(-2.0f * qp[0]);
        nx1p[qy] = pack2(-2.0f * qp[1]);
        nx2p[qy] = pack2(-2.0f * qp[2]);
    }

    // Paired-target records (32 B each):
    //   s_t[2r]   = (y0a, y0b, y1a, y1b)
    //   s_t[2r+1] = (y2a, y2b, |ya|^2, |yb|^2)
    __shared__ float4 s_t[2 * RECS];        // 16 KB, reused for merges

    {
        const float2* tb2 = (const float2*)(tset + ((size_t)b * NPTS + ts * TILE) * 3);
        for (int i = tid; i < RECS; i += TPB) {
            float2 e0 = tb2[3 * i + 0];     // (a0, a1)
            float2 e1 = tb2[3 * i + 1];     // (a2, b0)
            float2 e2 = tb2[3 * i + 2];     // (b1, b2)
            float na = fmaf(e0.x, e0.x, fmaf(e0.y, e0.y, e1.x * e1.x));
            float nb = fmaf(e1.y, e1.y, fmaf(e2.x, e2.x, e2.y * e2.y));
            s_t[2 * i]     = make_float4(e0.x, e1.y, e0.y, e2.x);
            s_t[2 * i + 1] = make_float4(e1.x, e2.y, na,   nb);
        }
    }
    __syncthreads();

    float mn0[QPT], mn1[QPT];
    #pragma unroll
    for (int qy = 0; qy < QPT; ++qy) { mn0[qy] = 3.402823466e38f; mn1[qy] = 3.402823466e38f; }

    // Group g scans records [g*RPG, (g+1)*RPG).
    {
        const ulonglong2* sp = (const ulonglong2*)s_t + (size_t)(2 * g * RPG);
        #pragma unroll 8
        for (int r = 0; r < RPG; ++r) {
            const ulonglong2 p = sp[2 * r];      // y0-pair, y1-pair
            const ulonglong2 q = sp[2 * r + 1];  // y2-pair, norm-pair
            #pragma unroll
            for (int qy = 0; qy < QPT; ++qy) {
                unsigned long long d;
                asm("fma.rn.f32x2 %0, %1, %2, %3;" : "=l"(d) : "l"(nx2p[qy]), "l"(q.x), "l"(q.y));
                asm("fma.rn.f32x2 %0, %1, %2, %3;" : "=l"(d) : "l"(nx1p[qy]), "l"(p.y), "l"(d));
                asm("fma.rn.f32x2 %0, %1, %2, %3;" : "=l"(d) : "l"(nx0p[qy]), "l"(p.x), "l"(d));
                float dlo, dhi;
                asm("mov.b64 {%0, %1}, %2;" : "=f"(dlo), "=f"(dhi) : "l"(d));
                mn0[qy] = fminf(mn0[qy], dlo);
                mn1[qy] = fminf(mn1[qy], dhi);
            }
        }
    }

    // ---- In-block merge across the 4 groups (reuse s_t). ----
    __syncthreads();
    float* s_mn  = (float*)s_t;              // [NGRP][QPB]
    float* s_red = (float*)s_t + NGRP * QPB; // [TPB]
    #pragma unroll
    for (int qy = 0; qy < QPT; ++qy)
        s_mn[g * QPB + qy * GSZ + lid] = fminf(mn0[qy], mn1[qy]);
    __syncthreads();

    // Column tid corresponds to query qbase + tid.
    float mnf = s_mn[tid];
    #pragma unroll
    for (int gg = 1; gg < NGRP; ++gg)
        mnf = fminf(mnf, s_mn[gg * QPB + tid]);

    // Publish this slice's raw mins; elect the last-arriving slice block.
    const int gid = (dir * B_DIM + b) * QBLK + blockIdx.x;   // 0..255
    g_min[(gid * TSPLIT + ts) * QPB + tid] = mnf;

    __shared__ int s_lastSlice;
    __syncthreads();                          // all g_min writes of block done
    if (tid == 0) {
        __threadfence();
        unsigned int old = atomicInc(&g_cnt1[gid], TSPLIT - 1);  // wraps -> reset
        s_lastSlice = (old == TSPLIT - 1);
    }
    __syncthreads();
    if (!s_lastSlice) return;

    // ---- Cross-slice merge + clamp + block partial sum (this block only). ----
    {
        const volatile float* vm = g_min + (size_t)gid * TSPLIT * QPB;
        float m = vm[tid];
        #pragma unroll
        for (int t = 1; t < TSPLIT; ++t)
            m = fminf(m, vm[t * QPB + tid]);

        const float* qp = qset + ((size_t)b * NPTS + qbase + tid) * 3;
        const float x0 = qp[0], x1 = qp[1], x2 = qp[2];
        const float xn = fmaf(x0, x0, fmaf(x1, x1, x2 * x2));
        float sq = fmaxf(m + xn, 0.0f) * (1.0f / (float)(B_DIM * NPTS));

        s_red[tid] = sq;
        __syncthreads();
        #pragma unroll
        for (int s = TPB / 2; s > 0; s >>= 1) {
            if (tid < s) s_red[tid] += s_red[tid + s];
            __syncthreads();
        }
    }

    __shared__ int s_lastGroup;
    if (tid == 0) {
        g_partials[gid] = s_red[0];
        __threadfence();
        unsigned int old = atomicInc(&g_cnt2, NGROUPS - 1);  // wraps -> reset
        s_lastGroup = (old == NGROUPS - 1);
    }
    __syncthreads();
    if (!s_lastGroup) return;

    // ---- Final fixed-order sum over the 256 group partials. ----
    {
        const volatile float* vp = g_partials;
        s_red[tid] = vp[tid];                 // NGROUPS == TPB == 256
        __syncthreads();
        #pragma unroll
        for (int s = TPB / 2; s > 0; s >>= 1) {
            if (tid < s) s_red[tid] += s_red[tid + s];
            __syncthreads();
        }
        if (tid == 0) out[0] = s_red[0];
    }
}

extern "C" void kernel_launch(void* const* d_in, const int* in_sizes, int n_in,
                              void* d_out, int out_size)
{
    const float* in_pts = (const float*)d_in[0];   // [8, 4096, 3]
    const float* tg_pts = (const float*)d_in[1];   // [8, 4096, 3]
    float* out = (float*)d_out;

    dim3 grid(QBLK, B_DIM, GRIDZ);
    chamfer_fused_kernel<<<grid, TPB>>>(in_pts, tg_pts, out);
}